// round 15
// baseline (speedup 1.0000x reference)
#include <cuda_runtime.h>
#include <cuda_bf16.h>

#define NMAX 100000
#define EMAX 3300000
#define DD 128

// Static device scratch (allocation-free). 16B-aligned for vector ld/st.
__device__ __align__(16) float g_bufA[NMAX * DD];
__device__ __align__(16) float g_bufB[NMAX * DD];
__device__ __align__(16) float g_dinv[NMAX];
__device__ int   g_deg[NMAX];
__device__ int   g_fill[NMAX];
__device__ int   g_rowptr[NMAX + 1];
__device__ int   g_bsum[256];
__device__ int   g_bsum2[256];
__device__ int   g_csrsrc[EMAX];
__device__ int   g_is64;
// weights: bf16 hi/lo splits [c][k]; fp32 WinT for phase B
__device__ __align__(16) __nv_bfloat16 g_WdHi[32 * 768];
__device__ __align__(16) __nv_bfloat16 g_WdLo[32 * 768];
__device__ __align__(16) __nv_bfloat16 g_WtHi[32 * 768];
__device__ __align__(16) __nv_bfloat16 g_WtLo[32 * 768];
__device__ __align__(16) __nv_bfloat16 g_Wg1Hi[128 * 128];
__device__ __align__(16) __nv_bfloat16 g_Wg1Lo[128 * 128];
__device__ __align__(16) __nv_bfloat16 g_Wg2Hi[128 * 128];
__device__ __align__(16) __nv_bfloat16 g_Wg2Lo[128 * 128];
__device__ __align__(16) __nv_bfloat16 g_Wo1Hi[128 * 128];
__device__ __align__(16) __nv_bfloat16 g_Wo1Lo[128 * 128];
__device__ __align__(16) float g_WinT[128 * 128];

__device__ __forceinline__ float lrelu(float v) { return v > 0.0f ? v : 0.01f * v; }

__device__ __forceinline__ void ffma2(unsigned long long& d, unsigned long long a, unsigned long long b) {
    asm("fma.rn.f32x2 %0, %1, %2, %0;" : "+l"(d) : "l"(a), "l"(b));
}
__device__ __forceinline__ float f2sum(unsigned long long v) {
    return __int_as_float((int)(v & 0xffffffffull)) + __int_as_float((int)(v >> 32));
}
__device__ __forceinline__ unsigned long long ld64(const float* p) {
    return *(const unsigned long long*)p;
}
__device__ __forceinline__ unsigned smem_u32(const void* p) {
    unsigned a;
    asm("{ .reg .u64 t; cvta.to.shared.u64 t, %1; cvt.u32.u64 %0, t; }" : "=r"(a) : "l"(p));
    return a;
}
__device__ __forceinline__ unsigned pack_bf16x2(float a, float b) {
    unsigned r;
    asm("cvt.rn.bf16x2.f32 %0, %1, %2;" : "=r"(r) : "f"(b), "f"(a));
    return r;
}
// split float2 -> (hi bf16x2, lo bf16x2)
__device__ __forceinline__ void split2(float x, float y, unsigned& hp, unsigned& lp) {
    hp = pack_bf16x2(x, y);
    float hx = __bfloat162float(__ushort_as_bfloat16((unsigned short)(hp & 0xffff)));
    float hy = __bfloat162float(__ushort_as_bfloat16((unsigned short)(hp >> 16)));
    lp = pack_bf16x2(x - hx, y - hy);
}
#define MMA_BF16(d0,d1,d2,d3,a0,a1,b)                                            \
    asm volatile("mma.sync.aligned.m16n8k8.row.col.f32.bf16.bf16.f32 "           \
                 "{%0,%1,%2,%3}, {%4,%5}, {%6}, {%0,%1,%2,%3};"                  \
                 : "+f"(d0), "+f"(d1), "+f"(d2), "+f"(d3)                        \
                 : "r"(a0), "r"(a1), "r"(b))

// Edge index fetch robust to int32-vs-int64 delivery of edge_index.
__device__ __forceinline__ int edge_at(const void* eidx, long long pos) {
    if (g_is64) return (int)(((const long long*)eidx)[pos]);
    return ((const int*)eidx)[pos];
}

__global__ void sniff_dtype(const int* __restrict__ p, int n) {
    if (threadIdx.x == 0 && blockIdx.x == 0) {
        int is64 = 1;
        for (int i = 0; i < 64; i++) {
            int lo = p[2 * i], hi = p[2 * i + 1];
            if (hi != 0 || lo < 0 || lo >= n) { is64 = 0; break; }
        }
        g_is64 = is64;
    }
}

// ---------------- weight transposes + bf16 hi/lo split ----------------
__global__ void transpose_all(
    const float* __restrict__ Wd, const float* __restrict__ Wt,
    const float* __restrict__ Win, const float* __restrict__ Wg1,
    const float* __restrict__ Wg2, const float* __restrict__ Wo1)
{
    int i = blockIdx.x * blockDim.x + threadIdx.x;
    if (i < 24576) {
        int r = i >> 5, c = i & 31;
        float v = Wd[i];
        __nv_bfloat16 h = __float2bfloat16(v);
        g_WdHi[c * 768 + r] = h;
        g_WdLo[c * 768 + r] = __float2bfloat16(v - __bfloat162float(h));
        return;
    }
    i -= 24576;
    if (i < 24576) {
        int r = i >> 5, c = i & 31;
        float v = Wt[i];
        __nv_bfloat16 h = __float2bfloat16(v);
        g_WtHi[c * 768 + r] = h;
        g_WtLo[c * 768 + r] = __float2bfloat16(v - __bfloat162float(h));
        return;
    }
    i -= 24576;
    if (i < 16384) { int r = i >> 7, c = i & 127; g_WinT[c * 128 + r] = Win[i]; return; }
    i -= 16384;
    if (i < 16384) {
        int r = i >> 7, c = i & 127;
        float v = Wg1[i];
        __nv_bfloat16 h = __float2bfloat16(v);
        g_Wg1Hi[c * 128 + r] = h;
        g_Wg1Lo[c * 128 + r] = __float2bfloat16(v - __bfloat162float(h));
        return;
    }
    i -= 16384;
    if (i < 16384) {
        int r = i >> 7, c = i & 127;
        float v = Wg2[i];
        __nv_bfloat16 h = __float2bfloat16(v);
        g_Wg2Hi[c * 128 + r] = h;
        g_Wg2Lo[c * 128 + r] = __float2bfloat16(v - __bfloat162float(h));
        return;
    }
    i -= 16384;
    if (i < 16384) {
        int r = i >> 7, c = i & 127;
        float v = Wo1[i];
        __nv_bfloat16 h = __float2bfloat16(v);
        g_Wo1Hi[c * 128 + r] = h;
        g_Wo1Lo[c * 128 + r] = __float2bfloat16(v - __bfloat162float(h));
        return;
    }
}

// ---------------- degree ----------------
__global__ void deg_zero(int n) {
    int i = blockIdx.x * blockDim.x + threadIdx.x;
    if (i < n) { g_deg[i] = 0; g_fill[i] = 0; }
}
__global__ void deg_count(const void* __restrict__ eidx, int ne) {
    int e = blockIdx.x * blockDim.x + threadIdx.x;
    if (e < ne) atomicAdd(&g_deg[edge_at(eidx, (long long)ne + e)], 1);
}
__global__ void deg_finish(int n) {
    int i = blockIdx.x * blockDim.x + threadIdx.x;
    if (i < n) g_dinv[i] = rsqrtf((float)(g_deg[i] + 1));
}

// ---------------- exclusive scan of g_deg -> g_rowptr ----------------
__global__ void __launch_bounds__(256) scan1(int n) {
    __shared__ int warpsum[8];
    int t = threadIdx.x;
    int i0 = blockIdx.x * 1024 + t * 4;
    int v0 = (i0 + 0 < n) ? g_deg[i0 + 0] : 0;
    int v1 = (i0 + 1 < n) ? g_deg[i0 + 1] : 0;
    int v2 = (i0 + 2 < n) ? g_deg[i0 + 2] : 0;
    int v3 = (i0 + 3 < n) ? g_deg[i0 + 3] : 0;
    int tsum = v0 + v1 + v2 + v3;
    int x = tsum;
    #pragma unroll
    for (int o = 1; o < 32; o <<= 1) {
        int y = __shfl_up_sync(0xffffffffu, x, o);
        if ((t & 31) >= o) x += y;
    }
    if ((t & 31) == 31) warpsum[t >> 5] = x;
    __syncthreads();
    if (t < 32) {
        int w = (t < 8) ? warpsum[t] : 0;
        int xx = w;
        #pragma unroll
        for (int o = 1; o < 8; o <<= 1) {
            int y = __shfl_up_sync(0xffffffffu, xx, o);
            if (t >= o) xx += y;
        }
        if (t < 8) warpsum[t] = xx - w;
    }
    __syncthreads();
    int ex = x - tsum + warpsum[t >> 5];
    if (i0 + 0 < n) g_rowptr[i0 + 0] = ex;
    if (i0 + 1 < n) g_rowptr[i0 + 1] = ex + v0;
    if (i0 + 2 < n) g_rowptr[i0 + 2] = ex + v0 + v1;
    if (i0 + 3 < n) g_rowptr[i0 + 3] = ex + v0 + v1 + v2;
    if (t == 255) g_bsum[blockIdx.x] = ex + tsum;
}
__global__ void __launch_bounds__(128) scan2(int nb) {
    __shared__ int ws[4];
    int t = threadIdx.x;
    int v = (t < nb) ? g_bsum[t] : 0;
    int x = v;
    #pragma unroll
    for (int o = 1; o < 32; o <<= 1) {
        int y = __shfl_up_sync(0xffffffffu, x, o);
        if ((t & 31) >= o) x += y;
    }
    if ((t & 31) == 31) ws[t >> 5] = x;
    __syncthreads();
    if (t < 32) {
        int w = (t < 4) ? ws[t] : 0;
        int xx = w;
        #pragma unroll
        for (int o = 1; o < 4; o <<= 1) {
            int y = __shfl_up_sync(0xffffffffu, xx, o);
            if (t >= o) xx += y;
        }
        if (t < 4) ws[t] = xx - w;
    }
    __syncthreads();
    g_bsum2[t] = x - v + ws[t >> 5];
}
__global__ void __launch_bounds__(256) scan3(int n, int ne) {
    int t = threadIdx.x;
    int add = g_bsum2[blockIdx.x];
    int i0 = blockIdx.x * 1024 + t * 4;
    #pragma unroll
    for (int j = 0; j < 4; j++)
        if (i0 + j < n) g_rowptr[i0 + j] += add;
    if (blockIdx.x == 0 && t == 0) g_rowptr[n] = ne;
}

__global__ void csr_fill(const void* __restrict__ eidx, int ne) {
    int e = blockIdx.x * blockDim.x + threadIdx.x;
    if (e >= ne) return;
    int s = edge_at(eidx, e);
    int d = edge_at(eidx, (long long)ne + e);
    int pos = g_rowptr[d] + atomicAdd(&g_fill[d], 1);
    g_csrsrc[pos] = s;
}

// ---------------- fused feature kernel: mma.sync bf16 hi/lo phase A ----------------
#define KS  200
#define X0S 134
#define KF_SMEM 68352

__global__ void __launch_bounds__(256) kfeat(
    const float* __restrict__ des, const float* __restrict__ tweet,
    const float* __restrict__ nump, const float* __restrict__ catp,
    const float* __restrict__ bd, const float* __restrict__ bt,
    const float* __restrict__ bn, const float* __restrict__ bc,
    const float* __restrict__ Wn, const float* __restrict__ Wc,
    const float* __restrict__ bin, int n)
{
    extern __shared__ char sm8[];
    unsigned smb = smem_u32(sm8);
    unsigned short* xh = (unsigned short*)sm8;
    unsigned short* xl = (unsigned short*)(sm8 + 12800);
    unsigned short* wh = (unsigned short*)(sm8 + 25600);
    unsigned short* wl = (unsigned short*)(sm8 + 38400);
    float* x0 = (float*)(sm8 + 51200);

    int t = threadIdx.x, lane = t & 31, wid = t >> 5;
    int node0 = blockIdx.x * 32;
    int m0 = (wid & 1) * 16;
    int c0 = (wid >> 1) * 8;
    int g = lane >> 2, tq = lane & 3;

    int ami = lane >> 3, ar = lane & 7;
    unsigned aBase = smb + ((ami < 2) ? 0u : 12800u)
                   + (unsigned)(m0 + ((ami & 1) ? 8 : 0) + ar) * 400u;
    int blane = lane & 15;
    unsigned bBase = smb + 25600u + ((blane < 8) ? 0u : 12800u)
                   + (unsigned)(c0 + (blane & 7)) * 400u;

    // division-free staging map: 256 thr = 32 rows x 8 slots, 6 float4 per slot
    int sm = t >> 3, sq0 = t & 7;

    for (int side = 0; side < 2; side++) {
        const float* X = side ? tweet : des;
        const __nv_bfloat16* WHg = side ? g_WtHi : g_WdHi;
        const __nv_bfloat16* WLg = side ? g_WtLo : g_WdLo;
        float d0 = 0.f, d1 = 0.f, d2 = 0.f, d3 = 0.f;

        for (int chunk = 0; chunk < 4; chunk++) {
            int k0 = chunk * 192;
            __syncthreads();
            {
                int row = min(node0 + sm, n - 1);
                const float4* src = (const float4*)(X + (size_t)row * 768 + k0);
                #pragma unroll
                for (int j = 0; j < 6; j++) {
                    int q = sq0 + 8 * j;
                    float4 v = src[q];
                    unsigned h0, l0p, h1, l1p;
                    split2(v.x, v.y, h0, l0p);
                    split2(v.z, v.w, h1, l1p);
                    *(uint2*)(xh + sm * KS + 4 * q) = make_uint2(h0, h1);
                    *(uint2*)(xl + sm * KS + 4 * q) = make_uint2(l0p, l1p);
                }
            }
            {
                const uint2* sh = (const uint2*)(WHg + sm * 768 + k0);
                const uint2* sl = (const uint2*)(WLg + sm * 768 + k0);
                #pragma unroll
                for (int j = 0; j < 6; j++) {
                    int q = sq0 + 8 * j;
                    *(uint2*)(wh + sm * KS + 4 * q) = sh[q];
                    *(uint2*)(wl + sm * KS + 4 * q) = sl[q];
                }
            }
            __syncthreads();

            unsigned aaddr = aBase, baddr = bBase;
            #pragma unroll 6
            for (int s = 0; s < 24; s++) {
                unsigned a0, a1, a2, a3, b0, b1;
                asm volatile("ldmatrix.sync.aligned.m8n8.x4.shared.b16 {%0,%1,%2,%3}, [%4];"
                             : "=r"(a0), "=r"(a1), "=r"(a2), "=r"(a3) : "r"(aaddr));
                asm volatile("ldmatrix.sync.aligned.m8n8.x2.shared.b16 {%0,%1}, [%2];"
                             : "=r"(b0), "=r"(b1) : "r"(baddr));
                MMA_BF16(d0, d1, d2, d3, a0, a1, b0);
                MMA_BF16(d0, d1, d2, d3, a0, a1, b1);
                MMA_BF16(d0, d1, d2, d3, a2, a3, b0);
                aaddr += 16;
                baddr += 16;
            }
        }
        const float* bias = side ? bt : bd;
        int cc = c0 + 2 * tq;
        float b0f = bias[cc], b1f = bias[cc + 1];
        x0[(m0 + g) * X0S + side * 32 + cc]         = lrelu(d0 + b0f);
        x0[(m0 + g) * X0S + side * 32 + cc + 1]     = lrelu(d1 + b1f);
        x0[(m0 + g + 8) * X0S + side * 32 + cc]     = lrelu(d2 + b0f);
        x0[(m0 + g + 8) * X0S + side * 32 + cc + 1] = lrelu(d3 + b1f);
    }

    // num/cat features: cols 64..127
    for (int o = t; o < 32 * 64; o += 256) {
        int m = o >> 6, c = o & 63;
        int row = min(node0 + m, n - 1);
        float v;
        if (c < 32) {
            v = bn[c];
            const float* xp = nump + (size_t)row * 6;
            #pragma unroll
            for (int k = 0; k < 6; k++) v += xp[k] * Wn[k * 32 + c];
        } else {
            int cc2 = c - 32;
            v = bc[cc2];
            const float* xp = catp + (size_t)row * 11;
            #pragma unroll
            for (int k = 0; k < 11; k++) v += xp[k] * Wc[k * 32 + cc2];
        }
        x0[m * X0S + 64 + c] = lrelu(v);
    }
    __syncthreads();

    // phase B: x1 = lrelu(x0 @ Win + bin) -> g_bufA (f32x2)
    {
        int cg2 = t >> 3, ng2 = t & 7;
        int cb0 = cg2 * 4;
        unsigned long long acc[4][4];
        #pragma unroll
        for (int i = 0; i < 4; i++)
            #pragma unroll
            for (int j = 0; j < 4; j++) acc[i][j] = 0;

        #pragma unroll 4
        for (int kk = 0; kk < 64; kk++) {
            int k = 2 * kk;
            unsigned long long x2[4];
            #pragma unroll
            for (int j = 0; j < 4; j++) x2[j] = ld64(x0 + (ng2 + 8 * j) * X0S + k);
            #pragma unroll
            for (int i = 0; i < 4; i++) {
                unsigned long long w2 = ld64(g_WinT + (cb0 + i) * 128 + k);
                #pragma unroll
                for (int j = 0; j < 4; j++) ffma2(acc[i][j], x2[j], w2);
            }
        }
        #pragma unroll
        for (int i = 0; i < 4; i++) {
            float b = bin[cb0 + i];
            #pragma unroll
            for (int j = 0; j < 4; j++) {
                int node = node0 + ng2 + 8 * j;
                if (node < n)
                    g_bufA[(size_t)node * 128 + cb0 + i] = lrelu(f2sum(acc[i][j]) + b);
            }
        }
    }
}

// ---------------- 128x128 GEMM via mma.sync: g_bufA @ W -> g_bufB ----------------
// 32 nodes/block, 256 thr = 8 warps: (w&1) m-tile, (w>>1)*32 cols (4 n8-tiles).
// B fragments loaded directly from global bf16 (lane-addressed), no W smem.
#define GS 136   // x stage stride (272 B rows, conflict-free, 16B-aligned)

__global__ void __launch_bounds__(256) gemm128(int sel, int n)
{
    __shared__ __align__(16) unsigned short xh[32 * GS];
    __shared__ __align__(16) unsigned short xl[32 * GS];
    const unsigned* WH = (const unsigned*)(sel ? g_Wg2Hi : g_Wg1Hi);
    const unsigned* WL = (const unsigned*)(sel ? g_Wg2Lo : g_Wg1Lo);
    int t = threadIdx.x, lane = t & 31, w = t >> 5;
    int node0 = blockIdx.x * 32;

    {
        int sm = t >> 3, sq0 = t & 7;
        int row = min(node0 + sm, n - 1);
        const float2* src = (const float2*)(g_bufA + (size_t)row * 128);
        #pragma unroll
        for (int j = 0; j < 8; j++) {
            int q = sq0 + 8 * j;
            float2 v = src[q];
            unsigned hp, lp;
            split2(v.x, v.y, hp, lp);
            *(unsigned*)(xh + sm * GS + 2 * q) = hp;
            *(unsigned*)(xl + sm * GS + 2 * q) = lp;
        }
    }
    __syncthreads();

    int m0 = (w & 1) * 16;
    int c0 = (w >> 1) * 32;                   // 4 warps x 32 cols = 128 cols
    int ami = lane >> 3, ar = lane & 7;
    unsigned aBase = (ami < 2 ? smem_u32(xh) : smem_u32(xl))
                   + (unsigned)(m0 + ((ami & 1) ? 8 : 0) + ar) * 272u;
    int bn_ = lane >> 2, bk = (lane & 3) * 2;

    float d[4][4];
    #pragma unroll
    for (int i = 0; i < 4; i++)
        #pragma unroll
        for (int j = 0; j < 4; j++) d[i][j] = 0.f;

    #pragma unroll 4
    for (int s = 0; s < 16; s++) {
        unsigned a0, a1, a2, a3;
        asm volatile("ldmatrix.sync.aligned.m8n8.x4.shared.b16 {%0,%1,%2,%3}, [%4];"
                     : "=r"(a0), "=r"(a1), "=r"(a2), "=r"(a3) : "r"(aBase + s * 16));
        int k0 = s * 8;
        #pragma unroll
        for (int nt = 0; nt < 4; nt++) {
            int idx = ((c0 + nt * 8 + bn_) * 128 + k0 + bk) >> 1;
            unsigned bh = WH[idx], bl = WL[idx];
            MMA_BF16(d[nt][0], d[nt][1], d[nt][2], d[nt][3], a0, a1, bh);
            MMA_BF16(d[nt][0], d[nt][1], d[nt][2], d[nt][3], a0, a1, bl);
            MMA_BF16(d[nt][0], d[nt][1], d[nt][2], d[nt][3], a2, a3, bh);
        }
    }

    int g = lane >> 2, tq = lane & 3;
    int nodeA = node0 + m0 + g, nodeB = nodeA + 8;
    #pragma unroll
    for (int nt = 0; nt < 4; nt++) {
        int c = c0 + nt * 8 + 2 * tq;
        if (nodeA < n) {
            g_bufB[(size_t)nodeA * 128 + c]     = d[nt][0];
            g_bufB[(size_t)nodeA * 128 + c + 1] = d[nt][1];
        }
        if (nodeB < n) {
            g_bufB[(size_t)nodeB * 128 + c]     = d[nt][2];
            g_bufB[(size_t)nodeB * 128 + c + 1] = d[nt][3];
        }
    }
}

// ---------------- CSR gather aggregation (fused self-loop + bias) ----------------
__global__ void __launch_bounds__(256) gather(const float* __restrict__ bias, int n)
{
    int gid = blockIdx.x * blockDim.x + threadIdx.x;
    int node = gid >> 5;
    int lane = gid & 31;
    if (node >= n) return;

    const float4* Y4 = (const float4*)g_bufB;
    float wd = g_dinv[node];
    float4 y = Y4[(size_t)node * 32 + lane];
    float4 acc, acc2;
    acc.x = wd * y.x; acc.y = wd * y.y; acc.z = wd * y.z; acc.w = wd * y.w;
    acc2.x = 0.f; acc2.y = 0.f; acc2.z = 0.f; acc2.w = 0.f;

    int lo = g_rowptr[node], hi = g_rowptr[node + 1];
    int e = lo;
    for (; e + 2 <= hi; e += 2) {
        int s0 = g_csrsrc[e], s1 = g_csrsrc[e + 1];
        float w0 = g_dinv[s0], w1 = g_dinv[s1];
        float4 a4 = Y4[(size_t)s0 * 32 + lane];
        float4 b4 = Y4[(size_t)s1 * 32 + lane];
        acc.x += w0 * a4.x; acc.y += w0 * a4.y; acc.z += w0 * a4.z; acc.w += w0 * a4.w;
        acc2.x += w1 * b4.x; acc2.y += w1 * b4.y; acc2.z += w1 * b4.z; acc2.w += w1 * b4.w;
    }
    if (e < hi) {
        int s = g_csrsrc[e];
        float w = g_dinv[s];
        float4 ys = Y4[(size_t)s * 32 + lane];
        acc.x += w * ys.x; acc.y += w * ys.y; acc.z += w * ys.z; acc.w += w * ys.w;
    }
    acc.x += acc2.x; acc.y += acc2.y; acc.z += acc2.z; acc.w += acc2.w;

    float4 b4 = ((const float4*)bias)[lane];
    float4 o;
    o.x = wd * acc.x + b4.x; o.y = wd * acc.y + b4.y;
    o.z = wd * acc.z + b4.z; o.w = wd * acc.w + b4.w;
    ((float4*)g_bufA)[(size_t)node * 32 + lane] = o;
}

// ---------------- output head: mma phase1 + 128->2 projection ----------------
__global__ void __launch_bounds__(256) kout(
    const float* __restrict__ bo1,
    const float* __restrict__ Wo2, const float* __restrict__ bo2,
    float* __restrict__ out, int n)
{
    __shared__ __align__(16) unsigned short xh[32 * GS];
    __shared__ __align__(16) unsigned short xl[32 * GS];
    __shared__ float sa[32 * X0S];
    const unsigned* WH = (const unsigned*)g_Wo1Hi;
    const unsigned* WL = (const unsigned*)g_Wo1Lo;
    int t = threadIdx.x, lane = t & 31, w = t >> 5;
    int node0 = blockIdx.x * 32;

    {
        int sm = t >> 3, sq0 = t & 7;
        int row = min(node0 + sm, n - 1);
        const float2* src = (const float2*)(g_bufA + (size_t)row * 128);
        #pragma unroll
        for (int j = 0; j < 8; j++) {
            int q = sq0 + 8 * j;
            float2 v = src[q];
            unsigned hp, lp;
            split2(v.x, v.y, hp, lp);
            *(unsigned*)(xh + sm * GS + 2 * q) = hp;
            *(unsigned*)(xl + sm * GS + 2 * q) = lp;
        }
    }
    __syncthreads();

    int m0 = (w & 1) * 16;
    int c0 = (w >> 1) * 32;                   // full 128-col coverage
    int ami = lane >> 3, ar = lane & 7;
    unsigned aBase = (ami < 2 ? smem_u32(xh) : smem_u32(xl))
                   + (unsigned)(m0 + ((ami & 1) ? 8 : 0) + ar) * 272u;
    int bn_ = lane >> 2, bk = (lane & 3) * 2;

    float d[4][4];
    #pragma unroll
    for (int i = 0; i < 4; i++)
        #pragma unroll
        for (int j = 0; j < 4; j++) d[i][j] = 0.f;

    #pragma unroll 4
    for (int s = 0; s < 16; s++) {
        unsigned a0, a1, a2, a3;
        asm volatile("ldmatrix.sync.aligned.m8n8.x4.shared.b16 {%0,%1,%2,%3}, [%4];"
                     : "=r"(a0), "=r"(a1), "=r"(a2), "=r"(a3) : "r"(aBase + s * 16));
        int k0 = s * 8;
        #pragma unroll
        for (int nt = 0; nt < 4; nt++) {
            int idx = ((c0 + nt * 8 + bn_) * 128 + k0 + bk) >> 1;
            unsigned bh = WH[idx], bl = WL[idx];
            MMA_BF16(d[nt][0], d[nt][1], d[nt][2], d[nt][3], a0, a1, bh);
            MMA_BF16(d[nt][0], d[nt][1], d[nt][2], d[nt][3], a0, a1, bl);
            MMA_BF16(d[nt][0], d[nt][1], d[nt][2], d[nt][3], a2, a3, bh);
        }
    }

    int g = lane >> 2, tq = lane & 3;
    #pragma unroll
    for (int nt = 0; nt < 4; nt++) {
        int c = c0 + nt * 8 + 2 * tq;
        float b0f = bo1[c], b1f = bo1[c + 1];
        sa[(m0 + g) * X0S + c]         = lrelu(d[nt][0] + b0f);
        sa[(m0 + g) * X0S + c + 1]     = lrelu(d[nt][1] + b1f);
        sa[(m0 + g + 8) * X0S + c]     = lrelu(d[nt][2] + b0f);
        sa[(m0 + g + 8) * X0S + c + 1] = lrelu(d[nt][3] + b1f);
    }
    __syncthreads();

    if (t < 64) {
        int m = t >> 1, c = t & 1;
        float s = bo2[c];
        const float* row = sa + m * X0S;
        #pragma unroll 4
        for (int k = 0; k < 128; k++) s += row[k] * Wo2[k * 2 + c];
        int node = node0 + m;
        if (node < n) out[(size_t)node * 2 + c] = s;
    }
}

extern "C" void kernel_launch(void* const* d_in, const int* in_sizes, int n_in,
                              void* d_out, int out_size)
{
    const float* des   = (const float*)d_in[0];
    const float* tweet = (const float*)d_in[1];
    const float* nump  = (const float*)d_in[2];
    const float* catp  = (const float*)d_in[3];
    const void*  eidx  = d_in[4];
    const float* Wd  = (const float*)d_in[6];  const float* bd  = (const float*)d_in[7];
    const float* Wt  = (const float*)d_in[8];  const float* bt  = (const float*)d_in[9];
    const float* Wn  = (const float*)d_in[10]; const float* bn  = (const float*)d_in[11];
    const float* Wc  = (const float*)d_in[12]; const float* bc  = (const float*)d_in[13];
    const float* Win = (const float*)d_in[14]; const float* bin = (const float*)d_in[15];
    const float* Wg1 = (const float*)d_in[16]; const float* bg1 = (const float*)d_in[17];
    const float* Wg2 = (const float*)d_in[18]; const float* bg2 = (const float*)d_in[19];
    const float* Wo1 = (const float*)d_in[20]; const float* bo1 = (const float*)d_in[21];
    const float* Wo2 = (const float*)d_in[22]; const float* bo2 = (const float*)d_in[23];
    float* out = (float*)d_out;

    int n  = in_sizes[2] / 6;
    int ne = in_sizes[5];
    int nb = (n + 1023) / 1024;

    cudaFuncSetAttribute(kfeat, cudaFuncAttributeMaxDynamicSharedMemorySize, KF_SMEM);

    // kfeat stays at launch slot #4 (the profiled launch).
    sniff_dtype<<<1, 32>>>((const int*)eidx, n);                     // 1
    transpose_all<<<448, 256>>>(Wd, Wt, Win, Wg1, Wg2, Wo1);         // 2
    deg_zero<<<(n + 255) / 256, 256>>>(n);                           // 3
    int nblk32 = (n + 31) / 32;
    kfeat<<<nblk32, 256, KF_SMEM>>>(des, tweet, nump, catp,          // 4 (profiled)
                                    bd, bt, bn, bc, Wn, Wc, bin, n);
    deg_count<<<(ne + 255) / 256, 256>>>(eidx, ne);                  // 5
    deg_finish<<<(n + 255) / 256, 256>>>(n);                         // 6
    scan1<<<nb, 256>>>(n);
    scan2<<<1, 128>>>(nb);
    scan3<<<nb, 256>>>(n, ne);
    csr_fill<<<(ne + 255) / 256, 256>>>(eidx, ne);

    int gather_blocks = (n * 32 + 255) / 256;

    gemm128<<<nblk32, 256>>>(0, n);
    gather<<<gather_blocks, 256>>>(bg1, n);

    gemm128<<<nblk32, 256>>>(1, n);
    gather<<<gather_blocks, 256>>>(bg2, n);

    kout<<<nblk32, 256>>>(bo1, Wo2, bo2, out, n);
}